// round 10
// baseline (speedup 1.0000x reference)
#include <cuda_runtime.h>
#include <cuda_fp16.h>
#include <cuda_bf16.h>
#include <math_constants.h>

#define D 512
#define STEPS 6
#define NB 148
#define NT 512
#define NW 16
#define TW (NB * NW)
#define MAXN 100000
#define RING 8
#define ROWB 1024                      // bytes per bf16 row
#define WTILE (RING * ROWB)            // 8 KB per warp
#define DYNB (NW * WTILE)              // 128 KB dynamic smem

typedef unsigned long long u64;

// ---- device scratch (static; no allocations) ----
__device__ __align__(16) uint4 g_xh[MAXN * 64];       // bf16 copy of x (102.4 MB)
__device__ __align__(16) unsigned g_wih[2048 * 512];  // fp16 W_ih (4 MB)
__device__ __align__(16) unsigned g_whh[2048 * 256];  // fp16 W_hh (2 MB)
__device__ __align__(16) float g_ps[NB * D];
__device__ __align__(16) float g_pm[NB];
__device__ __align__(16) float g_pz[NB];
__device__ __align__(16) float g_ctx[STEPS * D];
__device__ __align__(16) float g_gates[4 * D];
__device__ __align__(16) float g_y[D];
__device__ volatile unsigned g_cnt[32];               // monotonic barrier counters

// ---- f32x2 packed helpers ----
__device__ __forceinline__ u64 fma2(u64 a, u64 b, u64 c) {
    u64 d; asm("fma.rn.f32x2 %0, %1, %2, %3;" : "=l"(d) : "l"(a), "l"(b), "l"(c)); return d;
}
__device__ __forceinline__ u64 mul2(u64 a, u64 b) {
    u64 d; asm("mul.rn.f32x2 %0, %1, %2;" : "=l"(d) : "l"(a), "l"(b)); return d;
}
__device__ __forceinline__ u64 add2(u64 a, u64 b) {
    u64 d; asm("add.rn.f32x2 %0, %1, %2;" : "=l"(d) : "l"(a), "l"(b)); return d;
}
__device__ __forceinline__ u64 bcast2(float v) {
    u64 d; asm("mov.b64 %0, {%1, %1};" : "=l"(d) : "f"(v)); return d;
}
__device__ __forceinline__ u64 pack2(float a, float b) {
    u64 d; asm("mov.b64 %0, {%1, %2};" : "=l"(d) : "f"(a), "f"(b)); return d;
}
__device__ __forceinline__ void unpack2(u64 v, float& a, float& b) {
    asm("mov.b64 {%0, %1}, %2;" : "=f"(a), "=f"(b) : "l"(v));
}
__device__ __forceinline__ u64 bf2tof2(unsigned w) {
    u64 d;
    asm("{\n\t"
        ".reg .b32 lo, hi;\n\t"
        "shl.b32 lo, %1, 16;\n\t"
        "and.b32 hi, %1, 0xffff0000;\n\t"
        "mov.b64 %0, {lo, hi};\n\t"
        "}" : "=l"(d) : "r"(w));
    return d;
}
__device__ __forceinline__ unsigned f2bf2(float a, float b) {
    __nv_bfloat162 h = __floats2bfloat162_rn(a, b);
    return *reinterpret_cast<unsigned*>(&h);
}
__device__ __forceinline__ u64 h2tof2(unsigned hh) {
    __half2 h = *reinterpret_cast<__half2*>(&hh);
    float2 f = __half22float2(h);
    return pack2(f.x, f.y);
}
__device__ __forceinline__ unsigned f2toh2(float a, float b) {
    __half2 h = __floats2half2_rn(a, b);
    return *reinterpret_cast<unsigned*>(&h);
}

// ---- cp.async helpers ----
__device__ __forceinline__ void cpa16(unsigned saddr, const void* gptr) {
    asm volatile("cp.async.cg.shared.global [%0], [%1], 16;"
                 :: "r"(saddr), "l"(gptr));
}
#define CPA_COMMIT()   asm volatile("cp.async.commit_group;")
#define CPA_WAIT(n)    asm volatile("cp.async.wait_group %0;" :: "n"(n))
#define CPA_WAIT_ALL() asm volatile("cp.async.wait_all;")

__device__ __forceinline__ float warp_sum(float v) {
#pragma unroll
    for (int o = 16; o; o >>= 1) v += __shfl_xor_sync(0xffffffffu, v, o);
    return v;
}

// Grid barrier: monotonic epoch counters -> replay-safe.
__device__ __forceinline__ void gbar(int k) {
    __syncthreads();
    if (threadIdx.x == 0) {
        __threadfence();
        unsigned prev = atomicAdd((unsigned*)(g_cnt + k), 1u);
        unsigned target = (prev / gridDim.x + 1u) * gridDim.x;
        while (g_cnt[k] < target) __nanosleep(64);
        __threadfence();
    }
    __syncthreads();
}

__device__ __forceinline__ float dot2(const u64* v, const u64* hq) {
    u64 d0 = mul2(v[0], hq[0]);
    u64 d1 = mul2(v[1], hq[1]);
    d0 = fma2(v[2], hq[2], d0);
    d1 = fma2(v[3], hq[3], d1);
    d0 = fma2(v[4], hq[4], d0);
    d1 = fma2(v[5], hq[5], d1);
    d0 = fma2(v[6], hq[6], d0);
    d1 = fma2(v[7], hq[7], d1);
    float a, b;
    unpack2(add2(d0, d1), a, b);
    return a + b;
}

// paired warp reduction: two partials -> both sums broadcast
__device__ __forceinline__ void reduce2(float p0, float p1, int lane,
                                        float& s0, float& s1) {
    const bool odd = lane & 1;
    float give = odd ? p0 : p1;
    float keep = odd ? p1 : p0;
    keep += __shfl_xor_sync(0xffffffffu, give, 1);
    keep += __shfl_xor_sync(0xffffffffu, keep, 2);
    keep += __shfl_xor_sync(0xffffffffu, keep, 4);
    keep += __shfl_xor_sync(0xffffffffu, keep, 8);
    keep += __shfl_xor_sync(0xffffffffu, keep, 16);
    s0 = __shfl_sync(0xffffffffu, keep, 0);
    s1 = __shfl_sync(0xffffffffu, keep, 1);
}

extern __shared__ char dynsmem[];       // 128 KB: warp rings / combine scratch (aliased)

__global__ __launch_bounds__(NT, 1) void s2sK(const float* __restrict__ x,
                                              const float* __restrict__ W_ih,
                                              const float* __restrict__ W_hh,
                                              const float* __restrict__ b_ih,
                                              const float* __restrict__ b_hh,
                                              const float* __restrict__ W_proj,
                                              const float* __restrict__ b_proj,
                                              float* __restrict__ out,
                                              int N) {
    float* s_big = (float*)dynsmem;                  // aliased onto the rings
    __shared__ __align__(16) float s_h[D];
    __shared__ __align__(16) float s_c[D];
    __shared__ __align__(16) float s_ctx[D];
    __shared__ float s_m[NW], s_z[NW];
    __shared__ float s_w[NB];

    const int t    = threadIdx.x;
    const int wi   = t >> 5;
    const int lane = t & 31;
    const int b    = blockIdx.x;
    const int gw   = b * NW + wi;
    const int n_w  = (N - gw + TW - 1) / TW;         // rows owned by this warp
    int bk = 0;

    char* myring = dynsmem + (size_t)wi * WTILE;
    const unsigned ring_u32 =
        (unsigned)__cvta_generic_to_shared(myring) + (unsigned)(lane * 16);

    s_h[t] = 0.f;
    s_c[t] = 0.f;
    __syncthreads();

    for (int s = 0; s < STEPS; s++) {
        float m, Z;
        u64 acc[8];
#pragma unroll
        for (int i = 0; i < 8; i++) acc[i] = 0ull;

        if (s == 0) {
            // ===== Step 0: h == 0 -> ctx0 = mean(x). Emit bf16 copy of x. =====
            const float4* __restrict__ x4 = (const float4*)x;
            int cnt = 0;

            float4 R0[4], R1[4], R2[4];
#pragma unroll
            for (int i = 0; i < 4; i++) {
                R0[i] = make_float4(0, 0, 0, 0);
                R1[i] = make_float4(0, 0, 0, 0);
                R2[i] = make_float4(0, 0, 0, 0);
            }
            auto ld0 = [&](float4* v, int r) {
                if (r < N) {
                    const float4* row = x4 + (size_t)r * 128 + lane;
#pragma unroll
                    for (int i = 0; i < 4; i++) v[i] = __ldcs(row + i * 32);
                }
            };
            auto pr0 = [&](const float4* v, int r) {
#pragma unroll
                for (int i = 0; i < 4; i++) {
                    acc[2 * i]     = add2(acc[2 * i],     pack2(v[i].x, v[i].y));
                    acc[2 * i + 1] = add2(acc[2 * i + 1], pack2(v[i].z, v[i].w));
                }
                cnt++;
                uint4 u0, u1;
                u0.x = f2bf2(v[0].x, v[0].y);  u0.y = f2bf2(v[0].z, v[0].w);
                u0.z = f2bf2(v[1].x, v[1].y);  u0.w = f2bf2(v[1].z, v[1].w);
                u1.x = f2bf2(v[2].x, v[2].y);  u1.y = f2bf2(v[2].z, v[2].w);
                u1.z = f2bf2(v[3].x, v[3].y);  u1.w = f2bf2(v[3].z, v[3].w);
                uint4* dst = g_xh + (size_t)r * 64 + lane;
                __stcg(dst, u0);
                __stcg(dst + 32, u1);
            };

            int r = gw;
            ld0(R0, r); ld0(R1, r + TW); ld0(R2, r + 2 * TW);
            while (r < N) {
                pr0(R0, r); ld0(R0, r + 3 * TW); r += TW;
                if (r >= N) break;
                pr0(R1, r); ld0(R1, r + 3 * TW); r += TW;
                if (r >= N) break;
                pr0(R2, r); ld0(R2, r + 3 * TW); r += TW;
            }
            m = 0.f;
            Z = (float)cnt;

            // ---- one-time fp16 conversion of LSTM weights (grid-strided) ----
            {
                const float4* w4 = (const float4*)W_ih;
                uint2* dih = (uint2*)g_wih;
                for (int i = b * NT + t; i < 2048 * 1024 / 4; i += NB * NT) {
                    const float4 v = w4[i];
                    uint2 u; u.x = f2toh2(v.x, v.y); u.y = f2toh2(v.z, v.w);
                    __stcg(dih + i, u);
                }
                const float4* u4 = (const float4*)W_hh;
                uint2* dhh = (uint2*)g_whh;
                for (int i = b * NT + t; i < 2048 * 512 / 4; i += NB * NT) {
                    const float4 v = u4[i];
                    uint2 u; u.x = f2toh2(v.x, v.y); u.y = f2toh2(v.z, v.w);
                    __stcg(dhh + i, u);
                }
            }
        } else {
            // ===== Steps 1..5: cp.async-staged attention over bf16 copy =======
            const bool fwd = !(s & 1);   // serpentine
            const ulonglong2* h2 = (const ulonglong2*)s_h;
            u64 hq[8];
#pragma unroll
            for (int i = 0; i < 4; i++) {
                ulonglong2 q = h2[i * 32 + lane];
                hq[2 * i] = q.x; hq[2 * i + 1] = q.y;
            }
            m = -CUDART_INF_F;
            Z = 0.f;

            // issue one row (clamped source; warp-uniform index math)
            auto issue_row = [&](int j) {
                const int idx = min(gw + j * TW, N - 1);
                const long long ph = fwd ? idx : (N - 1 - idx);
                const uint4* src = g_xh + ph * 64 + lane;
                const unsigned dst = ring_u32 + (unsigned)((j & (RING - 1)) * ROWB);
                cpa16(dst, src);
                cpa16(dst + 512, src + 32);
                CPA_COMMIT();
            };
            // consume pair (rows k, k+1) from the ring
            auto proc2 = [&](int k, bool row1ok) {
                const uint4* s0 = (const uint4*)(myring + (k & (RING - 1)) * ROWB);
                const uint4* s1 = (const uint4*)(myring + ((k + 1) & (RING - 1)) * ROWB);
                const uint4 r0a = s0[lane], r0b = s0[32 + lane];
                const uint4 r1a = s1[lane], r1b = s1[32 + lane];
                u64 v0[8], v1[8];
                v0[0] = bf2tof2(r0a.x); v0[1] = bf2tof2(r0a.y);
                v0[2] = bf2tof2(r0a.z); v0[3] = bf2tof2(r0a.w);
                v0[4] = bf2tof2(r0b.x); v0[5] = bf2tof2(r0b.y);
                v0[6] = bf2tof2(r0b.z); v0[7] = bf2tof2(r0b.w);
                v1[0] = bf2tof2(r1a.x); v1[1] = bf2tof2(r1a.y);
                v1[2] = bf2tof2(r1a.z); v1[3] = bf2tof2(r1a.w);
                v1[4] = bf2tof2(r1b.x); v1[5] = bf2tof2(r1b.y);
                v1[6] = bf2tof2(r1b.z); v1[7] = bf2tof2(r1b.w);
                float p0 = dot2(v0, hq);
                float p1 = dot2(v1, hq);
                if (!row1ok) p1 = -CUDART_INF_F;     // warp-uniform
                float s0v, s1v;
                reduce2(p0, p1, lane, s0v, s1v);
                const float pm = fmaxf(s0v, s1v);
                if (pm > m) {
                    const float sc = __expf(m - pm);
                    m = pm;
                    Z *= sc;
                    const u64 sc2 = bcast2(sc);
#pragma unroll
                    for (int i = 0; i < 8; i++) acc[i] = mul2(acc[i], sc2);
                }
                const float e0 = __expf(s0v - m);
                const float e1 = __expf(s1v - m);
                Z += e0 + e1;
                const u64 e02 = bcast2(e0);
                const u64 e12 = bcast2(e1);
#pragma unroll
                for (int i = 0; i < 8; i++) acc[i] = fma2(v0[i], e02, acc[i]);
#pragma unroll
                for (int i = 0; i < 8; i++) acc[i] = fma2(v1[i], e12, acc[i]);
            };

            // prologue: fill the 8-row ring
#pragma unroll
            for (int j = 0; j < RING; j++) issue_row(j);

            const int P = (n_w + 1) >> 1;
            const bool lastFull = !(n_w & 1);
            int jn = RING;                           // next row to issue
            int k  = 0;                              // next row to consume
            for (int p = 0; p < P; p++) {
                CPA_WAIT(RING - 2);                  // oldest 2 rows resident
                proc2(k, (p < P - 1) || lastFull);
                issue_row(jn);      jn++;
                issue_row(jn);      jn++;
                k += 2;
            }
            CPA_WAIT_ALL();                          // drain before s_big alias reuse
        }

        // ===== block-combine of 16 warp partials =====
        if (lane == 0) { s_m[wi] = m; s_z[wi] = Z; }
        __syncthreads();
        {
            float mb = -CUDART_INF_F;
#pragma unroll
            for (int w = 0; w < NW; w++) mb = fmaxf(mb, s_m[w]);
            const float sc = __expf(m - mb);
            float4* dst = (float4*)&s_big[wi * D];
#pragma unroll
            for (int i = 0; i < 4; i++) {
                float x0, x1, x2f, x3;
                unpack2(acc[2 * i], x0, x1);
                unpack2(acc[2 * i + 1], x2f, x3);
                dst[i * 32 + lane] = make_float4(x0 * sc, x1 * sc, x2f * sc, x3 * sc);
            }
            __syncthreads();
            {
                float ss = 0.f;
#pragma unroll
                for (int w = 0; w < NW; w++) ss += s_big[w * D + t];
                __stcg(&g_ps[b * D + t], ss);
            }
            if (t == 0) {
                float zb = 0.f;
                for (int w = 0; w < NW; w++) zb += s_z[w] * __expf(s_m[w] - mb);
                __stcg(&g_pm[b], mb);
                __stcg(&g_pz[b], zb);
            }
        }
        gbar(bk++);

        // ===== Phase B: combine partials -> ctx (blocks 0..15, 32 dims each) ====
        if (b < 16) {
            float lm = (t < NB) ? __ldcg(&g_pm[t]) : -CUDART_INF_F;
            s_big[t] = lm;
            __syncthreads();
            for (int o = 256; o; o >>= 1) {
                if (t < o) s_big[t] = fmaxf(s_big[t], s_big[t + o]);
                __syncthreads();
            }
            const float M2 = s_big[0];
            __syncthreads();
            float zz = 0.f;
            if (t < NB) {
                const float w = __expf(__ldcg(&g_pm[t]) - M2);
                s_w[t] = w;
                zz = w * __ldcg(&g_pz[t]);
            }
            s_big[t] = zz;
            __syncthreads();
            for (int o = 256; o; o >>= 1) {
                if (t < o) s_big[t] += s_big[t + o];
                __syncthreads();
            }
            const float Zs = s_big[0];
            __syncthreads();

            const int dim = t & 31, c = t >> 5;          // 16 chunks of 32 dims
            const int gd = b * 32 + dim;
            float a = 0.f;
#pragma unroll 4
            for (int q = c; q < NB; q += 16) a += __ldcg(&g_ps[q * D + gd]) * s_w[q];
            s_big[c * 32 + dim] = a;
            __syncthreads();
            if (t < 32) {
                float ssum = 0.f;
#pragma unroll
                for (int c2 = 0; c2 < 16; c2++) ssum += s_big[c2 * 32 + t];
                __stcg(&g_ctx[s * D + b * 32 + t], ssum / Zs);
            }
        }
        gbar(bk++);

        if (s == STEPS - 1) break;   // last LSTM update unused

        // ===== Phase C: gate rows (warp per row, fp16 weights) =====
        for (int i = t; i < D; i += NT) s_ctx[i] = __ldcg(&g_ctx[s * D + i]);
        __syncthreads();
        {
            const int row = b + NB * wi;
            if (row < 4 * D) {
                const uint4* wr = (const uint4*)g_wih + (size_t)row * 128;
                const uint4* ur = (const uint4*)g_whh + (size_t)row * 64;
                const ulonglong2* cc = (const ulonglong2*)s_ctx;
                const ulonglong2* hh = (const ulonglong2*)s_h;
                u64 a2 = 0ull;
#pragma unroll
                for (int j = 0; j < 2; j++) {            // ctx half of W_ih
                    const uint4 w = __ldcg(wr + j * 32 + lane);
                    const int i2 = (j * 32 + lane) * 2;
                    const ulonglong2 c0 = cc[i2], c1 = cc[i2 + 1];
                    a2 = fma2(h2tof2(w.x), c0.x, a2);
                    a2 = fma2(h2tof2(w.y), c0.y, a2);
                    a2 = fma2(h2tof2(w.z), c1.x, a2);
                    a2 = fma2(h2tof2(w.w), c1.y, a2);
                }
#pragma unroll
                for (int j = 0; j < 2; j++) {            // h half of W_ih
                    const uint4 w = __ldcg(wr + (j + 2) * 32 + lane);
                    const int i2 = (j * 32 + lane) * 2;
                    const ulonglong2 c0 = hh[i2], c1 = hh[i2 + 1];
                    a2 = fma2(h2tof2(w.x), c0.x, a2);
                    a2 = fma2(h2tof2(w.y), c0.y, a2);
                    a2 = fma2(h2tof2(w.z), c1.x, a2);
                    a2 = fma2(h2tof2(w.w), c1.y, a2);
                }
#pragma unroll
                for (int j = 0; j < 2; j++) {            // W_hh @ h
                    const uint4 w = __ldcg(ur + j * 32 + lane);
                    const int i2 = (j * 32 + lane) * 2;
                    const ulonglong2 c0 = hh[i2], c1 = hh[i2 + 1];
                    a2 = fma2(h2tof2(w.x), c0.x, a2);
                    a2 = fma2(h2tof2(w.y), c0.y, a2);
                    a2 = fma2(h2tof2(w.z), c1.x, a2);
                    a2 = fma2(h2tof2(w.w), c1.y, a2);
                }
                float aa, ab;
                unpack2(a2, aa, ab);
                float a = aa + ab;
                a = warp_sum(a);
                if (lane == 0) __stcg(&g_gates[row], a);
            }
        }
        gbar(bk++);

        // LSTM pointwise (redundant per block; h/c in smem)
        {
            const int j = t;
            float gi = __ldcg(&g_gates[j])         + b_ih[j]         + b_hh[j];
            float gf = __ldcg(&g_gates[D + j])     + b_ih[D + j]     + b_hh[D + j];
            float gg = __ldcg(&g_gates[2 * D + j]) + b_ih[2 * D + j] + b_hh[2 * D + j];
            float go = __ldcg(&g_gates[3 * D + j]) + b_ih[3 * D + j] + b_hh[3 * D + j];
            gi = 1.f / (1.f + __expf(-gi));
            gf = 1.f / (1.f + __expf(-gf));
            gg = tanhf(gg);
            go = 1.f / (1.f + __expf(-go));
            const float cn = gf * s_c[j] + gi * gg;
            s_c[j] = cn;
            s_h[j] = go * tanhf(cn);
        }
        __syncthreads();
    }

    // ===== Projection: warp per output row =====
    for (int i = t; i < STEPS * D; i += NT) s_big[i] = __ldcg(&g_ctx[i]);
    __syncthreads();
    {
        const int row = b + NB * wi;
        if (row < D) {
            const float4* wr = (const float4*)(W_proj + (size_t)row * (STEPS * D));
            const float4* c4 = (const float4*)s_big;
            float a = 0.f;
#pragma unroll
            for (int i = 0; i < 24; i++) {
                const float4 w = wr[i * 32 + lane], v = c4[i * 32 + lane];
                a += w.x * v.x + w.y * v.y + w.z * v.z + w.w * v.w;
            }
            a = warp_sum(a);
            if (lane == 0) __stcg(&g_y[row], a + b_proj[row]);
        }
    }
    gbar(bk++);

    // ===== Final softmax (block 0) =====
    if (b == 0) {
        const float v = __ldcg(&g_y[t]);
        s_big[t] = v;
        __syncthreads();
        for (int o = 256; o; o >>= 1) {
            if (t < o) s_big[t] = fmaxf(s_big[t], s_big[t + o]);
            __syncthreads();
        }
        const float M2 = s_big[0];
        __syncthreads();
        const float e = __expf(v - M2);
        s_big[t] = e;
        __syncthreads();
        for (int o = 256; o; o >>= 1) {
            if (t < o) s_big[t] += s_big[t + o];
            __syncthreads();
        }
        out[t] = e / s_big[0];
    }
}

extern "C" void kernel_launch(void* const* d_in, const int* in_sizes, int n_in,
                              void* d_out, int out_size) {
    const float* x      = (const float*)d_in[0];
    const float* W_ih   = (const float*)d_in[1];
    const float* W_hh   = (const float*)d_in[2];
    const float* b_ih   = (const float*)d_in[3];
    const float* b_hh   = (const float*)d_in[4];
    const float* W_proj = (const float*)d_in[5];
    const float* b_proj = (const float*)d_in[6];
    float* out = (float*)d_out;
    const int N = in_sizes[0] / D;

    cudaFuncSetAttribute(s2sK, cudaFuncAttributeMaxDynamicSharedMemorySize, DYNB);
    s2sK<<<NB, NT, DYNB>>>(x, W_ih, W_hh, b_ih, b_hh, W_proj, b_proj, out, N);
}

// round 11
// speedup vs baseline: 3.4573x; 3.4573x over previous
#include <cuda_runtime.h>
#include <cuda_fp16.h>
#include <cuda_bf16.h>
#include <math_constants.h>

#define D 512
#define STEPS 6
#define NB 148
#define NT 512
#define NW 16
#define TW (NB * NW)
#define MAXN 100000

typedef unsigned long long u64;

// ---- device scratch (static; no allocations) ----
__device__ __align__(16) uint4 g_xh[MAXN * 64];       // bf16 copy of x (102.4 MB)
__device__ __align__(16) unsigned g_wih[2048 * 512];  // fp16 W_ih (4 MB, half2 words)
__device__ __align__(16) unsigned g_whh[2048 * 256];  // fp16 W_hh (2 MB)
__device__ __align__(16) float g_ps[NB * D];
__device__ __align__(16) float g_pm[NB];
__device__ __align__(16) float g_pz[NB];
__device__ __align__(16) float g_ctx[STEPS * D];
__device__ __align__(16) float g_gates[4 * D];
__device__ __align__(16) float g_y[D];
__device__ volatile unsigned g_cnt[32];               // monotonic barrier counters

// ---- f32x2 packed helpers ----
__device__ __forceinline__ u64 fma2(u64 a, u64 b, u64 c) {
    u64 d; asm("fma.rn.f32x2 %0, %1, %2, %3;" : "=l"(d) : "l"(a), "l"(b), "l"(c)); return d;
}
__device__ __forceinline__ u64 mul2(u64 a, u64 b) {
    u64 d; asm("mul.rn.f32x2 %0, %1, %2;" : "=l"(d) : "l"(a), "l"(b)); return d;
}
__device__ __forceinline__ u64 add2(u64 a, u64 b) {
    u64 d; asm("add.rn.f32x2 %0, %1, %2;" : "=l"(d) : "l"(a), "l"(b)); return d;
}
__device__ __forceinline__ u64 bcast2(float v) {
    u64 d; asm("mov.b64 %0, {%1, %1};" : "=l"(d) : "f"(v)); return d;
}
__device__ __forceinline__ u64 pack2(float a, float b) {
    u64 d; asm("mov.b64 %0, {%1, %2};" : "=l"(d) : "f"(a), "f"(b)); return d;
}
__device__ __forceinline__ void unpack2(u64 v, float& a, float& b) {
    asm("mov.b64 {%0, %1}, %2;" : "=f"(a), "=f"(b) : "l"(v));
}
// bf16x2 word -> f32x2 (2 cheap ALU ops)
__device__ __forceinline__ u64 bf2tof2(unsigned w) {
    u64 d;
    asm("{\n\t"
        ".reg .b32 lo, hi;\n\t"
        "shl.b32 lo, %1, 16;\n\t"
        "and.b32 hi, %1, 0xffff0000;\n\t"
        "mov.b64 %0, {lo, hi};\n\t"
        "}" : "=l"(d) : "r"(w));
    return d;
}
// pack two fp32 -> bf16x2 by TRUNCATION: single PRMT (selects high bytes).
// byte sel 0x7632: out = {a[2],a[3],b[2],b[3]} = bf16(a) | bf16(b)<<16
__device__ __forceinline__ unsigned f2bf2t(float a, float b) {
    unsigned r;
    asm("prmt.b32 %0, %1, %2, 0x7632;"
        : "=r"(r) : "r"(__float_as_uint(a)), "r"(__float_as_uint(b)));
    return r;
}
// fp16x2 -> f32x2 (phase C only; off the hot path)
__device__ __forceinline__ u64 h2tof2(unsigned hh) {
    __half2 h = *reinterpret_cast<__half2*>(&hh);
    float2 f = __half22float2(h);
    return pack2(f.x, f.y);
}
__device__ __forceinline__ unsigned f2toh2(float a, float b) {
    __half2 h = __floats2half2_rn(a, b);
    return *reinterpret_cast<unsigned*>(&h);
}

__device__ __forceinline__ float warp_sum(float v) {
#pragma unroll
    for (int o = 16; o; o >>= 1) v += __shfl_xor_sync(0xffffffffu, v, o);
    return v;
}

// Grid barrier: monotonic epoch counters -> replay-safe.
__device__ __forceinline__ void gbar(int k) {
    __syncthreads();
    if (threadIdx.x == 0) {
        __threadfence();
        unsigned prev = atomicAdd((unsigned*)(g_cnt + k), 1u);
        unsigned target = (prev / gridDim.x + 1u) * gridDim.x;
        while (g_cnt[k] < target) __nanosleep(64);
        __threadfence();
    }
    __syncthreads();
}

__device__ __forceinline__ float dot2(const u64* v, const u64* hq) {
    u64 d0 = mul2(v[0], hq[0]);
    u64 d1 = mul2(v[1], hq[1]);
    d0 = fma2(v[2], hq[2], d0);
    d1 = fma2(v[3], hq[3], d1);
    d0 = fma2(v[4], hq[4], d0);
    d1 = fma2(v[5], hq[5], d1);
    d0 = fma2(v[6], hq[6], d0);
    d1 = fma2(v[7], hq[7], d1);
    float a, b;
    unpack2(add2(d0, d1), a, b);
    return a + b;
}

// paired warp reduction: two partials -> both sums broadcast
__device__ __forceinline__ void reduce2(float p0, float p1, int lane,
                                        float& s0, float& s1) {
    const bool odd = lane & 1;
    float give = odd ? p0 : p1;
    float keep = odd ? p1 : p0;
    keep += __shfl_xor_sync(0xffffffffu, give, 1);
    keep += __shfl_xor_sync(0xffffffffu, keep, 2);
    keep += __shfl_xor_sync(0xffffffffu, keep, 4);
    keep += __shfl_xor_sync(0xffffffffu, keep, 8);
    keep += __shfl_xor_sync(0xffffffffu, keep, 16);
    s0 = __shfl_sync(0xffffffffu, keep, 0);
    s1 = __shfl_sync(0xffffffffu, keep, 1);
}

__global__ __launch_bounds__(NT, 1) void s2sK(const float* __restrict__ x,
                                              const float* __restrict__ W_ih,
                                              const float* __restrict__ W_hh,
                                              const float* __restrict__ b_ih,
                                              const float* __restrict__ b_hh,
                                              const float* __restrict__ W_proj,
                                              const float* __restrict__ b_proj,
                                              float* __restrict__ out,
                                              int N) {
    __shared__ __align__(16) float s_big[NW * D];    // 32 KB
    __shared__ __align__(16) float s_h[D];
    __shared__ __align__(16) float s_c[D];
    __shared__ __align__(16) float s_ctx[D];
    __shared__ float s_m[NW], s_z[NW];
    __shared__ float s_w[NB];

    const int t    = threadIdx.x;
    const int wi   = t >> 5;
    const int lane = t & 31;
    const int b    = blockIdx.x;
    const int gw   = b * NW + wi;
    int bk = 0;

    s_h[t] = 0.f;
    s_c[t] = 0.f;
    __syncthreads();

    for (int s = 0; s < STEPS; s++) {
        float m, Z;
        u64 acc[8];
#pragma unroll
        for (int i = 0; i < 8; i++) acc[i] = 0ull;

        if (s == 0) {
            // ===== Step 0: h == 0 -> ctx0 = mean(x). Emit bf16 copy (PRMT pack).
            const float4* __restrict__ x4 = (const float4*)x;
            int cnt = 0;

            float4 R0[4], R1[4], R2[4], R3[4];
#pragma unroll
            for (int i = 0; i < 4; i++) {
                R0[i] = make_float4(0, 0, 0, 0);
                R1[i] = make_float4(0, 0, 0, 0);
                R2[i] = make_float4(0, 0, 0, 0);
                R3[i] = make_float4(0, 0, 0, 0);
            }
            auto ld0 = [&](float4* v, int r) {
                if (r < N) {
                    const float4* row = x4 + (size_t)r * 128 + lane;
#pragma unroll
                    for (int i = 0; i < 4; i++) v[i] = __ldcs(row + i * 32);
                }
            };
            auto pr0 = [&](const float4* v, int r) {
#pragma unroll
                for (int i = 0; i < 4; i++) {
                    acc[2 * i]     = add2(acc[2 * i],     pack2(v[i].x, v[i].y));
                    acc[2 * i + 1] = add2(acc[2 * i + 1], pack2(v[i].z, v[i].w));
                }
                cnt++;
                uint4 u0, u1;                 // 1 PRMT per word (truncation pack)
                u0.x = f2bf2t(v[0].x, v[0].y);  u0.y = f2bf2t(v[0].z, v[0].w);
                u0.z = f2bf2t(v[1].x, v[1].y);  u0.w = f2bf2t(v[1].z, v[1].w);
                u1.x = f2bf2t(v[2].x, v[2].y);  u1.y = f2bf2t(v[2].z, v[2].w);
                u1.z = f2bf2t(v[3].x, v[3].y);  u1.w = f2bf2t(v[3].z, v[3].w);
                uint4* dst = g_xh + (size_t)r * 64 + lane;
                __stcg(dst, u0);
                __stcg(dst + 32, u1);
            };

            int r = gw;
            ld0(R0, r); ld0(R1, r + TW); ld0(R2, r + 2 * TW); ld0(R3, r + 3 * TW);
            while (r < N) {
                pr0(R0, r); ld0(R0, r + 4 * TW); r += TW;
                if (r >= N) break;
                pr0(R1, r); ld0(R1, r + 4 * TW); r += TW;
                if (r >= N) break;
                pr0(R2, r); ld0(R2, r + 4 * TW); r += TW;
                if (r >= N) break;
                pr0(R3, r); ld0(R3, r + 4 * TW); r += TW;
            }
            m = 0.f;
            Z = (float)cnt;

            // ---- one-time fp16 conversion of LSTM weights (grid-strided) ----
            {
                const float4* w4 = (const float4*)W_ih;
                uint2* dih = (uint2*)g_wih;
                for (int i = b * NT + t; i < 2048 * 1024 / 4; i += NB * NT) {
                    const float4 v = w4[i];
                    uint2 u; u.x = f2toh2(v.x, v.y); u.y = f2toh2(v.z, v.w);
                    __stcg(dih + i, u);
                }
                const float4* u4 = (const float4*)W_hh;
                uint2* dhh = (uint2*)g_whh;
                for (int i = b * NT + t; i < 2048 * 512 / 4; i += NB * NT) {
                    const float4 v = u4[i];
                    uint2 u; u.x = f2toh2(v.x, v.y); u.y = f2toh2(v.z, v.w);
                    __stcg(dhh + i, u);
                }
            }
        } else {
            // ===== Steps 1..5: attention over bf16 copy, depth-3 pair pipeline ==
            const bool fwd = !(s & 1);   // serpentine
            const ulonglong2* h2 = (const ulonglong2*)s_h;
            u64 hq[8];
#pragma unroll
            for (int i = 0; i < 4; i++) {
                ulonglong2 q = h2[i * 32 + lane];
                hq[2 * i] = q.x; hq[2 * i + 1] = q.y;
            }
            m = -CUDART_INF_F;
            Z = 0.f;

            uint4 P0[4], P1[4], P2[4];
#pragma unroll
            for (int i = 0; i < 4; i++) {
                P0[i] = make_uint4(0, 0, 0, 0);
                P1[i] = make_uint4(0, 0, 0, 0);
                P2[i] = make_uint4(0, 0, 0, 0);
            }

            // default cached loads: L1 persists across steps in this persistent
            // kernel; serpentine reversal makes the prior step's tail L1-resident.
            auto ldpair = [&](uint4* v, int rr) {
                if (rr < N) {
                    const long long ph = fwd ? rr : (N - 1 - rr);
                    const uint4* p = g_xh + ph * 64 + lane;
                    v[0] = p[0];
                    v[1] = p[32];
                }
                const int r2 = rr + TW;
                if (r2 < N) {
                    const long long ph = fwd ? r2 : (N - 1 - r2);
                    const uint4* p = g_xh + ph * 64 + lane;
                    v[2] = p[0];
                    v[3] = p[32];
                }
            };
            auto proc = [&](const uint4* raw, int rr) {
                u64 v0[8], v1[8];
                v0[0] = bf2tof2(raw[0].x); v0[1] = bf2tof2(raw[0].y);
                v0[2] = bf2tof2(raw[0].z); v0[3] = bf2tof2(raw[0].w);
                v0[4] = bf2tof2(raw[1].x); v0[5] = bf2tof2(raw[1].y);
                v0[6] = bf2tof2(raw[1].z); v0[7] = bf2tof2(raw[1].w);
                v1[0] = bf2tof2(raw[2].x); v1[1] = bf2tof2(raw[2].y);
                v1[2] = bf2tof2(raw[2].z); v1[3] = bf2tof2(raw[2].w);
                v1[4] = bf2tof2(raw[3].x); v1[5] = bf2tof2(raw[3].y);
                v1[6] = bf2tof2(raw[3].z); v1[7] = bf2tof2(raw[3].w);
                float p0 = dot2(v0, hq);
                float p1 = dot2(v1, hq);
                if (rr + TW >= N) p1 = -CUDART_INF_F;   // warp-uniform
                float s0, s1;
                reduce2(p0, p1, lane, s0, s1);
                const float pm = fmaxf(s0, s1);
                if (pm > m) {
                    const float sc = __expf(m - pm);
                    m = pm;
                    Z *= sc;
                    const u64 sc2 = bcast2(sc);
#pragma unroll
                    for (int i = 0; i < 8; i++) acc[i] = mul2(acc[i], sc2);
                }
                const float e0 = __expf(s0 - m);
                const float e1 = __expf(s1 - m);
                Z += e0 + e1;
                const u64 e02 = bcast2(e0);
                const u64 e12 = bcast2(e1);
#pragma unroll
                for (int i = 0; i < 8; i++) acc[i] = fma2(v0[i], e02, acc[i]);
#pragma unroll
                for (int i = 0; i < 8; i++) acc[i] = fma2(v1[i], e12, acc[i]);
            };

            int rr = gw;                         // pair = (rr, rr+TW), stride 2*TW
            ldpair(P0, rr);
            ldpair(P1, rr + 2 * TW);
            ldpair(P2, rr + 4 * TW);
            while (rr < N) {
                proc(P0, rr); ldpair(P0, rr + 6 * TW); rr += 2 * TW;
                if (rr >= N) break;
                proc(P1, rr); ldpair(P1, rr + 6 * TW); rr += 2 * TW;
                if (rr >= N) break;
                proc(P2, rr); ldpair(P2, rr + 6 * TW); rr += 2 * TW;
            }
        }

        // ===== block-combine of 16 warp partials =====
        if (lane == 0) { s_m[wi] = m; s_z[wi] = Z; }
        __syncthreads();
        {
            float mb = -CUDART_INF_F;
#pragma unroll
            for (int w = 0; w < NW; w++) mb = fmaxf(mb, s_m[w]);
            const float sc = __expf(m - mb);
            float4* dst = (float4*)&s_big[wi * D];
#pragma unroll
            for (int i = 0; i < 4; i++) {
                float x0, x1, x2f, x3;
                unpack2(acc[2 * i], x0, x1);
                unpack2(acc[2 * i + 1], x2f, x3);
                dst[i * 32 + lane] = make_float4(x0 * sc, x1 * sc, x2f * sc, x3 * sc);
            }
            __syncthreads();
            {
                float ss = 0.f;
#pragma unroll
                for (int w = 0; w < NW; w++) ss += s_big[w * D + t];
                __stcg(&g_ps[b * D + t], ss);
            }
            if (t == 0) {
                float zb = 0.f;
                for (int w = 0; w < NW; w++) zb += s_z[w] * __expf(s_m[w] - mb);
                __stcg(&g_pm[b], mb);
                __stcg(&g_pz[b], zb);
            }
        }
        gbar(bk++);

        // ===== Phase B: combine partials -> ctx (blocks 0..15, 32 dims each) ====
        if (b < 16) {
            float lm = (t < NB) ? __ldcg(&g_pm[t]) : -CUDART_INF_F;
            s_big[t] = lm;
            __syncthreads();
            for (int o = 256; o; o >>= 1) {
                if (t < o) s_big[t] = fmaxf(s_big[t], s_big[t + o]);
                __syncthreads();
            }
            const float M2 = s_big[0];
            __syncthreads();
            float zz = 0.f;
            if (t < NB) {
                const float w = __expf(__ldcg(&g_pm[t]) - M2);
                s_w[t] = w;
                zz = w * __ldcg(&g_pz[t]);
            }
            s_big[t] = zz;
            __syncthreads();
            for (int o = 256; o; o >>= 1) {
                if (t < o) s_big[t] += s_big[t + o];
                __syncthreads();
            }
            const float Zs = s_big[0];
            __syncthreads();

            const int dim = t & 31, c = t >> 5;          // 16 chunks of 32 dims
            const int gd = b * 32 + dim;
            float a = 0.f;
#pragma unroll 4
            for (int q = c; q < NB; q += 16) a += __ldcg(&g_ps[q * D + gd]) * s_w[q];
            s_big[c * 32 + dim] = a;
            __syncthreads();
            if (t < 32) {
                float ssum = 0.f;
#pragma unroll
                for (int c2 = 0; c2 < 16; c2++) ssum += s_big[c2 * 32 + t];
                __stcg(&g_ctx[s * D + b * 32 + t], ssum / Zs);
            }
        }
        gbar(bk++);

        if (s == STEPS - 1) break;   // last LSTM update unused

        // ===== Phase C: gate rows (warp per row, fp16 weights) =====
        for (int i = t; i < D; i += NT) s_ctx[i] = __ldcg(&g_ctx[s * D + i]);
        __syncthreads();
        {
            const int row = b + NB * wi;
            if (row < 4 * D) {
                const uint4* wr = (const uint4*)g_wih + (size_t)row * 128;
                const uint4* ur = (const uint4*)g_whh + (size_t)row * 64;
                const ulonglong2* cc = (const ulonglong2*)s_ctx;
                const ulonglong2* hh = (const ulonglong2*)s_h;
                u64 a2 = 0ull;
#pragma unroll
                for (int j = 0; j < 2; j++) {            // ctx half of W_ih
                    const uint4 w = __ldcg(wr + j * 32 + lane);
                    const int i2 = (j * 32 + lane) * 2;
                    const ulonglong2 c0 = cc[i2], c1 = cc[i2 + 1];
                    a2 = fma2(h2tof2(w.x), c0.x, a2);
                    a2 = fma2(h2tof2(w.y), c0.y, a2);
                    a2 = fma2(h2tof2(w.z), c1.x, a2);
                    a2 = fma2(h2tof2(w.w), c1.y, a2);
                }
#pragma unroll
                for (int j = 0; j < 2; j++) {            // h half of W_ih
                    const uint4 w = __ldcg(wr + (j + 2) * 32 + lane);
                    const int i2 = (j * 32 + lane) * 2;
                    const ulonglong2 c0 = hh[i2], c1 = hh[i2 + 1];
                    a2 = fma2(h2tof2(w.x), c0.x, a2);
                    a2 = fma2(h2tof2(w.y), c0.y, a2);
                    a2 = fma2(h2tof2(w.z), c1.x, a2);
                    a2 = fma2(h2tof2(w.w), c1.y, a2);
                }
#pragma unroll
                for (int j = 0; j < 2; j++) {            // W_hh @ h
                    const uint4 w = __ldcg(ur + j * 32 + lane);
                    const int i2 = (j * 32 + lane) * 2;
                    const ulonglong2 c0 = hh[i2], c1 = hh[i2 + 1];
                    a2 = fma2(h2tof2(w.x), c0.x, a2);
                    a2 = fma2(h2tof2(w.y), c0.y, a2);
                    a2 = fma2(h2tof2(w.z), c1.x, a2);
                    a2 = fma2(h2tof2(w.w), c1.y, a2);
                }
                float aa, ab;
                unpack2(a2, aa, ab);
                float a = aa + ab;
                a = warp_sum(a);
                if (lane == 0) __stcg(&g_gates[row], a);
            }
        }
        gbar(bk++);

        // LSTM pointwise (redundant per block; h/c in smem)
        {
            const int j = t;
            float gi = __ldcg(&g_gates[j])         + b_ih[j]         + b_hh[j];
            float gf = __ldcg(&g_gates[D + j])     + b_ih[D + j]     + b_hh[D + j];
            float gg = __ldcg(&g_gates[2 * D + j]) + b_ih[2 * D + j] + b_hh[2 * D + j];
            float go = __ldcg(&g_gates[3 * D + j]) + b_ih[3 * D + j] + b_hh[3 * D + j];
            gi = 1.f / (1.f + __expf(-gi));
            gf = 1.f / (1.f + __expf(-gf));
            gg = tanhf(gg);
            go = 1.f / (1.f + __expf(-go));
            const float cn = gf * s_c[j] + gi * gg;
            s_c[j] = cn;
            s_h[j] = go * tanhf(cn);
        }
        __syncthreads();
    }

    // ===== Projection: warp per output row =====
    for (int i = t; i < STEPS * D; i += NT) s_big[i] = __ldcg(&g_ctx[i]);
    __syncthreads();
    {
        const int row = b + NB * wi;
        if (row < D) {
            const float4* wr = (const float4*)(W_proj + (size_t)row * (STEPS * D));
            const float4* c4 = (const float4*)s_big;
            float a = 0.f;
#pragma unroll
            for (int i = 0; i < 24; i++) {
                const float4 w = wr[i * 32 + lane], v = c4[i * 32 + lane];
                a += w.x * v.x + w.y * v.y + w.z * v.z + w.w * v.w;
            }
            a = warp_sum(a);
            if (lane == 0) __stcg(&g_y[row], a + b_proj[row]);
        }
    }
    gbar(bk++);

    // ===== Final softmax (block 0) =====
    if (b == 0) {
        const float v = __ldcg(&g_y[t]);
        s_big[t] = v;
        __syncthreads();
        for (int o = 256; o; o >>= 1) {
            if (t < o) s_big[t] = fmaxf(s_big[t], s_big[t + o]);
            __syncthreads();
        }
        const float M2 = s_big[0];
        __syncthreads();
        const float e = __expf(v - M2);
        s_big[t] = e;
        __syncthreads();
        for (int o = 256; o; o >>= 1) {
            if (t < o) s_big[t] += s_big[t + o];
            __syncthreads();
        }
        out[t] = e / s_big[0];
    }
}

extern "C" void kernel_launch(void* const* d_in, const int* in_sizes, int n_in,
                              void* d_out, int out_size) {
    const float* x      = (const float*)d_in[0];
    const float* W_ih   = (const float*)d_in[1];
    const float* W_hh   = (const float*)d_in[2];
    const float* b_ih   = (const float*)d_in[3];
    const float* b_hh   = (const float*)d_in[4];
    const float* W_proj = (const float*)d_in[5];
    const float* b_proj = (const float*)d_in[6];
    float* out = (float*)d_out;
    const int N = in_sizes[0] / D;

    s2sK<<<NB, NT>>>(x, W_ih, W_hh, b_ih, b_hh, W_proj, b_proj, out, N);
}